// round 5
// baseline (speedup 1.0000x reference)
#include <cuda_runtime.h>

// LIF membrane recurrence, HBM-bound streaming kernel.
//   mem[t] = 0.25 * mem[t-1] * (1 - spike[t-1]) + x[t] ; spike[t] = mem[t] > 0.5
// x: (8, 32, 128, 32, 32) fp32. 134 MB read + 134 MB write, zero reuse.
//
// History: R0/R3 baseline 36.1us kernel (DRAM 75%). Cache hints (.cs/.cg)
// regress ~+8.7us — keep default caching.
// R4: software pipeline with prefetch depth 2 (MLP_p1 8 -> 2) to cut
// cross-CTA L1tex-queue contention / CTA-completion spread. Loop is
// deliberately NOT unrolled so ptxas cannot re-hoist all 8 loads.

#define T_STEPS 8
#define INNER   (32 * 128 * 32 * 32)   // 4,194,304 elements per timestep
#define INNER4  (INNER / 4)            // 1,048,576 float4 sites

__global__ void lif_kernel(const float4* __restrict__ x, float4* __restrict__ out) {
    int i = blockIdx.x * blockDim.x + threadIdx.x;
    if (i >= INNER4) return;

    const float DECAY = 0.25f;
    const float THR   = 0.5f;

    // Prefetch pipeline: two timesteps in flight.
    float4 cur = x[i];
    float4 nxt = x[(size_t)INNER4 + i];

    float m0 = 0.f, m1 = 0.f, m2 = 0.f, m3 = 0.f;
    float s0 = 0.f, s1 = 0.f, s2 = 0.f, s3 = 0.f;

#pragma unroll 1
    for (int t = 0; t < T_STEPS; ++t) {
        float4 xv = cur;
        cur = nxt;
        if (t + 2 < T_STEPS) {
            nxt = x[(size_t)(t + 2) * INNER4 + i];
        }

        m0 = DECAY * m0 * (1.0f - s0) + xv.x;
        m1 = DECAY * m1 * (1.0f - s1) + xv.y;
        m2 = DECAY * m2 * (1.0f - s2) + xv.z;
        m3 = DECAY * m3 * (1.0f - s3) + xv.w;
        s0 = (m0 > THR) ? 1.0f : 0.0f;
        s1 = (m1 > THR) ? 1.0f : 0.0f;
        s2 = (m2 > THR) ? 1.0f : 0.0f;
        s3 = (m3 > THR) ? 1.0f : 0.0f;

        out[(size_t)t * INNER4 + i] = make_float4(s0, s1, s2, s3);
    }
}

extern "C" void kernel_launch(void* const* d_in, const int* in_sizes, int n_in,
                              void* d_out, int out_size) {
    const float4* x = (const float4*)d_in[0];
    float4* out = (float4*)d_out;
    int threads = 256;
    int blocks = (INNER4 + threads - 1) / threads;   // 4096
    lif_kernel<<<blocks, threads>>>(x, out);
}

// round 6
// speedup vs baseline: 1.0092x; 1.0092x over previous
#include <cuda_runtime.h>

// LIF membrane recurrence, HBM-bound streaming kernel.
//   mem[t] = 0.25 * mem[t-1] * (1 - spike[t-1]) + x[t] ; spike[t] = mem[t] > 0.5
// x: (8, 32, 128, 32, 32) fp32. 134 MB read + 134 MB write, zero reuse.
//
// History: R0/R3 baseline 36.1us kernel (DRAM 75%, 5.95 TB/s).
//   R1 (.cs ld+st)  -> +8.6us  : forces write stream to DRAM in-kernel. NO.
//   R2 (.cg loads)  -> +9.2us  : L1 bypass hurts vectorized stream. NO.
//   R4 (sw pipeline)-> +2.0us  : de-batching loads adds issue overhead. NO.
// R5: R0 shape + per-thread tile x2 (2 float4 per thread, warp-coherent),
// halving CTA count and per-byte index overhead. Front-batch all 16 loads.

#define T_STEPS 8
#define INNER   (32 * 128 * 32 * 32)   // 4,194,304 elements per timestep
#define INNER4  (INNER / 4)            // 1,048,576 float4 sites
#define TILE    2                      // float4s per thread

__global__ void lif_kernel(const float4* __restrict__ x, float4* __restrict__ out) {
    // Thread handles sites i and i + blockDim (warp-coherent, coalesced).
    int base = blockIdx.x * (blockDim.x * TILE) + threadIdx.x;

    const float DECAY = 0.25f;
    const float THR   = 0.5f;

    // Front-batch all 16 loads (8 timesteps x 2 sites): max MLP.
    float4 xv[T_STEPS][TILE];
#pragma unroll
    for (int t = 0; t < T_STEPS; ++t) {
#pragma unroll
        for (int j = 0; j < TILE; ++j) {
            xv[t][j] = x[(size_t)t * INNER4 + base + j * blockDim.x];
        }
    }

    float m[TILE][4] = {};
    float s[TILE][4] = {};

#pragma unroll
    for (int t = 0; t < T_STEPS; ++t) {
#pragma unroll
        for (int j = 0; j < TILE; ++j) {
            float4 v = xv[t][j];
            m[j][0] = DECAY * m[j][0] * (1.0f - s[j][0]) + v.x;
            m[j][1] = DECAY * m[j][1] * (1.0f - s[j][1]) + v.y;
            m[j][2] = DECAY * m[j][2] * (1.0f - s[j][2]) + v.z;
            m[j][3] = DECAY * m[j][3] * (1.0f - s[j][3]) + v.w;
            s[j][0] = (m[j][0] > THR) ? 1.0f : 0.0f;
            s[j][1] = (m[j][1] > THR) ? 1.0f : 0.0f;
            s[j][2] = (m[j][2] > THR) ? 1.0f : 0.0f;
            s[j][3] = (m[j][3] > THR) ? 1.0f : 0.0f;
            out[(size_t)t * INNER4 + base + j * blockDim.x] =
                make_float4(s[j][0], s[j][1], s[j][2], s[j][3]);
        }
    }
}

extern "C" void kernel_launch(void* const* d_in, const int* in_sizes, int n_in,
                              void* d_out, int out_size) {
    const float4* x = (const float4*)d_in[0];
    float4* out = (float4*)d_out;
    int threads = 256;
    int blocks = INNER4 / (threads * TILE);   // 2048, exact
    lif_kernel<<<blocks, threads>>>(x, out);
}